// round 6
// baseline (speedup 1.0000x reference)
#include <cuda_runtime.h>
#include <cuda_bf16.h>
#include <mma.h>
#include <cstdint>

using namespace nvcuda;

// ---------------- static scratch (no allocs allowed) ----------------
#define MAXN 10240
#define MAXE 330240
#define MAXW 320   // ceil(MAXN/32)

__device__ float   g_P[MAXN * 256];
__device__ float   g_Q[MAXN * 256];
__device__ float   g_nbr[MAXN * 256];
__device__ float   g_f2[MAXN * 256];
__device__ float   g_S1[MAXN * 256];
__device__ float   g_T1[MAXN * 256];
__device__ unsigned g_AB[MAXN * MAXW];
__device__ unsigned g_RB[MAXN * MAXW];
__device__ int     g_rowptr[MAXN + 1];
__device__ int     g_cursor[MAXN];
__device__ int     g_degcnt[MAXN];
__device__ int     g_csrcol[MAXE];
__device__ float   g_cnt2[MAXN];

// ---------------- zero scratch that accumulates ----------------
__global__ void zero_kernel(int n, int words) {
    size_t total = (size_t)n * words;
    for (size_t idx = (size_t)blockIdx.x * blockDim.x + threadIdx.x; idx < total;
         idx += (size_t)gridDim.x * blockDim.x) {
        g_AB[idx] = 0u;
        if (idx < (size_t)n) g_degcnt[idx] = 0;
    }
}

// ---------------- per-edge: degree count + adjacency bitset ----------------
__global__ void edge_prep_kernel(const int* __restrict__ row, const int* __restrict__ col,
                                 int E, int words) {
    int e = blockIdx.x * blockDim.x + threadIdx.x;
    if (e >= E) return;
    int r = row[e], c = col[e];
    atomicAdd(&g_degcnt[r], 1);
    atomicOr(&g_AB[(size_t)r * words + (c >> 5)], 1u << (c & 31));
}

// ---------------- scan v2: 256-thread chunked + warp-shuffle scan ----------------
__global__ void scan_kernel(int n) {
    __shared__ int sums[257];
    int t = threadIdx.x;                 // 256 threads
    int chunk = (n + 255) >> 8;
    int s0 = t * chunk; if (s0 > n) s0 = n;
    int s1 = s0 + chunk; if (s1 > n) s1 = n;
    int sum = 0;
    for (int i = s0; i < s1; i++) sum += g_degcnt[i];
    sums[t] = sum;
    __syncthreads();
    if (t < 32) {
        int vals[8];
        int g = 0;
#pragma unroll
        for (int k = 0; k < 8; k++) { vals[k] = sums[t * 8 + k]; g += vals[k]; }
        int inc = g;
#pragma unroll
        for (int off = 1; off < 32; off <<= 1) {
            int u = __shfl_up_sync(0xffffffffu, inc, off);
            if (t >= off) inc += u;
        }
        int exc = inc - g;
#pragma unroll
        for (int k = 0; k < 8; k++) { sums[t * 8 + k] = exc; exc += vals[k]; }
        if (t == 31) sums[256] = inc;
    }
    __syncthreads();
    int run = sums[t];
    for (int i = s0; i < s1; i++) {
        int v = g_degcnt[i];
        g_rowptr[i] = run; g_cursor[i] = run;
        run += v;
    }
    if (t == 0) g_rowptr[n] = sums[256];
}

// ---------------- CSR scatter ----------------
__global__ void scatter_kernel(const int* __restrict__ row, const int* __restrict__ col, int E) {
    int e = blockIdx.x * blockDim.x + threadIdx.x;
    if (e >= E) return;
    int r = row[e];
    int p = atomicAdd(&g_cursor[r], 1);
    g_csrcol[p] = col[e];
}

// ---------------- 1-hop: nbr_mean + 2-hop reach bitset + cnt2 ----------------
__global__ void hop1_kernel(const float* __restrict__ NT, int n, int words) {
    int i = blockIdx.x;
    int t = threadIdx.x;
    int t2 = 256 + t;
    int s0 = g_rowptr[i], s1 = g_rowptr[i + 1];
    unsigned w0 = 0u, w1 = 0u;
    float acc = 0.f;
    for (int p = s0; p < s1; p++) {
        int j = g_csrcol[p];
        const unsigned* abr = &g_AB[(size_t)j * words];
        if (t < words)  w0 |= abr[t];
        if (t2 < words) w1 |= abr[t2];
        acc += NT[(size_t)j * 256 + t];
    }
    int wi = i >> 5;
    unsigned sb = 1u << (i & 31);
    if (wi == t)  w0 &= ~sb;
    if (wi == t2) w1 &= ~sb;
    if (t < words)  g_RB[(size_t)i * words + t]  = w0;
    if (t2 < words) g_RB[(size_t)i * words + t2] = w1;

    int deg = s1 - s0;
    float inv = deg > 0 ? 1.f / (float)deg : 0.f;
    g_nbr[(size_t)i * 256 + t] = acc * inv;

    __shared__ int red[256];
    red[t] = __popc(w0) + __popc(w1);
    __syncthreads();
    for (int off = 128; off > 0; off >>= 1) {
        if (t < off) red[t] += red[t + off];
        __syncthreads();
    }
    if (t == 0) g_cnt2[i] = (float)red[0];
}

// ---------------- edge tokens: out2[e] = P[row[e]] + Q[col[e]] ----------------
__global__ void edge_tok_kernel(const int* __restrict__ row, const int* __restrict__ col,
                                float* __restrict__ out2, int E) {
    long long idx = (long long)blockIdx.x * blockDim.x + threadIdx.x;
    long long total = (long long)E * 64;
    if (idx >= total) return;
    int e = (int)(idx >> 6);
    int q = (int)(idx & 63);
    int r = row[e], c = col[e];
    float4 a = reinterpret_cast<const float4*>(g_P)[(size_t)r * 64 + q];
    float4 b = reinterpret_cast<const float4*>(g_Q)[(size_t)c * 64 + q];
    float4 o;
    o.x = a.x + b.x; o.y = a.y + b.y; o.z = a.z + b.z; o.w = a.w + b.w;
    reinterpret_cast<float4*>(out2)[idx] = o;
}

// ---------------- feat2 v3: column-split, 64 nodes x 128 cols per CTA ----------------
#define F2_MI 64
#define F2_TR 192
__global__ __launch_bounds__(256, 2)
void feat2_kernel(const float* __restrict__ NT, int n, int words) {
    extern __shared__ float tile[];                        // F2_TR*128 floats
    unsigned* smask = (unsigned*)(tile + F2_TR * 128);     // F2_MI*6 words

    int t = threadIdx.x;
    int w = t >> 5;
    int l = t & 31;
    int h = blockIdx.y;
    int i0 = blockIdx.x * F2_MI;
    int cbase = h * 128 + l * 4;

    float acc[8][4];
#pragma unroll
    for (int k = 0; k < 8; k++) {
        acc[k][0] = 0.f; acc[k][1] = 0.f; acc[k][2] = 0.f; acc[k][3] = 0.f;
    }

    int ntiles = (words + 5) / 6;
    for (int tb = 0; tb < ntiles; tb++) {
        int k0 = tb * F2_TR;
        for (int v = t; v < F2_TR * 32; v += 256) {
            int r = v >> 5;
            int c = (v & 31) << 2;
            int kk = k0 + r;
            float4 val = make_float4(0.f, 0.f, 0.f, 0.f);
            if (kk < n)
                val = *reinterpret_cast<const float4*>(&NT[(size_t)kk * 256 + h * 128 + c]);
            *reinterpret_cast<float4*>(&tile[r * 128 + c]) = val;
        }
        for (int v = t; v < F2_MI * 6; v += 256) {
            int m = v / 6, wl = v % 6;
            int i = i0 + m;
            int wd = tb * 6 + wl;
            smask[v] = (i < n && wd < words) ? g_RB[(size_t)i * words + wd] : 0u;
        }
        __syncthreads();
#pragma unroll
        for (int k = 0; k < 8; k++) {
            int m = w * 8 + k;
#pragma unroll
            for (int wl = 0; wl < 6; wl++) {
                unsigned mask = smask[m * 6 + wl];
                while (mask) {
                    int b = __ffs(mask) - 1;
                    mask &= mask - 1;
                    const float4 v =
                        *reinterpret_cast<const float4*>(&tile[((wl << 5) + b) * 128 + l * 4]);
                    acc[k][0] += v.x; acc[k][1] += v.y;
                    acc[k][2] += v.z; acc[k][3] += v.w;
                }
            }
        }
        __syncthreads();
    }
#pragma unroll
    for (int k = 0; k < 8; k++) {
        int i = i0 + w * 8 + k;
        if (i < n) {
            float c = g_cnt2[i];
            float inv = c > 0.f ? 1.f / c : 0.f;
            float4 o;
            o.x = acc[k][0] * inv; o.y = acc[k][1] * inv;
            o.z = acc[k][2] * inv; o.w = acc[k][3] * inv;
            *reinterpret_cast<float4*>(&g_f2[(size_t)i * 256 + cbase]) = o;
        }
    }
}

// ---------------- GEMM v6: wmma tf32 tensor-core, 128x128 tile, job-fused ----------------
// C[M,256] = act( [A0|A1|A2][M,K] @ W[K,256] + bias ), K = nblk*256.
// 8 warps, each owns a 32x64 strip (2x4 m16n16k8 acc fragments).
// tf32 conversion applied once per element at smem staging.
struct Job {
    const float* A0; const float* A1; const float* A2;
    const float* W;  const float* b;  float* C;
    int nblk; int relu;
};

#define TLDA 20    // As leading dim (floats)
#define TLDB 132   // Bs leading dim (floats)

__global__ __launch_bounds__(256)
void sgemm_kernel(Job j0, Job j1, Job j2, int M) {
    __shared__ __align__(32) float As[2][128 * TLDA];
    __shared__ __align__(32) float Bs[2][16 * TLDB];
    __shared__ __align__(32) float stage[8][16 * 20];

    int z = blockIdx.z;
    Job jb = (z == 0) ? j0 : ((z == 1) ? j1 : j2);
    const float* A0 = jb.A0;
    const float* A1 = jb.A1;
    const float* A2 = jb.A2;
    const float* W  = jb.W;
    const float* bias = jb.b;
    float* C = jb.C;
    int ntiles = jb.nblk << 4;
    int relu = jb.relu;

    int tid  = threadIdx.x;
    int warp = tid >> 5;
    int lane = tid & 31;
    int wm = warp >> 1;        // 0..3 : 32-row strip
    int wn = warp & 1;         // 0..1 : 64-col strip
    int row0 = blockIdx.y * 128;
    int col0 = blockIdx.x * 128;

    // global load maps
    int a_r = tid >> 1;              // 0..127
    int a_c = (tid & 1) << 3;        // 0 or 8
    int b_r = tid >> 4;              // 0..15
    int b_c = (tid & 15) << 3;       // 0..120
    int gar = row0 + a_r;

    wmma::fragment<wmma::accumulator, 16, 16, 8, float> acc[2][4];
#pragma unroll
    for (int i = 0; i < 2; i++)
#pragma unroll
        for (int j = 0; j < 4; j++) wmma::fill_fragment(acc[i][j], 0.f);

    // ---- prologue: tile 0 -> buf 0 (convert to tf32 at staging) ----
    {
        float4 av0 = make_float4(0.f, 0.f, 0.f, 0.f);
        float4 av1 = make_float4(0.f, 0.f, 0.f, 0.f);
        if (gar < M) {
            av0 = *reinterpret_cast<const float4*>(&A0[(size_t)gar * 256 + a_c]);
            av1 = *reinterpret_cast<const float4*>(&A0[(size_t)gar * 256 + a_c + 4]);
        }
        float* ap = &As[0][a_r * TLDA + a_c];
        ap[0] = wmma::__float_to_tf32(av0.x); ap[1] = wmma::__float_to_tf32(av0.y);
        ap[2] = wmma::__float_to_tf32(av0.z); ap[3] = wmma::__float_to_tf32(av0.w);
        ap[4] = wmma::__float_to_tf32(av1.x); ap[5] = wmma::__float_to_tf32(av1.y);
        ap[6] = wmma::__float_to_tf32(av1.z); ap[7] = wmma::__float_to_tf32(av1.w);
        float4 bv0 = *reinterpret_cast<const float4*>(&W[(size_t)b_r * 256 + col0 + b_c]);
        float4 bv1 = *reinterpret_cast<const float4*>(&W[(size_t)b_r * 256 + col0 + b_c + 4]);
        float* bp = &Bs[0][b_r * TLDB + b_c];
        bp[0] = wmma::__float_to_tf32(bv0.x); bp[1] = wmma::__float_to_tf32(bv0.y);
        bp[2] = wmma::__float_to_tf32(bv0.z); bp[3] = wmma::__float_to_tf32(bv0.w);
        bp[4] = wmma::__float_to_tf32(bv1.x); bp[5] = wmma::__float_to_tf32(bv1.y);
        bp[6] = wmma::__float_to_tf32(bv1.z); bp[7] = wmma::__float_to_tf32(bv1.w);
    }
    __syncthreads();

    int buf = 0;
    for (int t = 0; t < ntiles; t++) {
        bool have_next = (t + 1 < ntiles);
        float4 av0 = make_float4(0.f, 0.f, 0.f, 0.f);
        float4 av1 = make_float4(0.f, 0.f, 0.f, 0.f);
        float4 bv0, bv1;
        if (have_next) {
            int kt = (t + 1) << 4;
            const float* Ap = (kt < 256) ? A0 : ((kt < 512) ? A1 : A2);
            int ko = kt & 255;
            if (gar < M) {
                av0 = *reinterpret_cast<const float4*>(&Ap[(size_t)gar * 256 + ko + a_c]);
                av1 = *reinterpret_cast<const float4*>(&Ap[(size_t)gar * 256 + ko + a_c + 4]);
            }
            bv0 = *reinterpret_cast<const float4*>(&W[(size_t)(kt + b_r) * 256 + col0 + b_c]);
            bv1 = *reinterpret_cast<const float4*>(&W[(size_t)(kt + b_r) * 256 + col0 + b_c + 4]);
        }

        // ---- tensor-core compute on current buffer ----
        const float* Asb = As[buf];
        const float* Bsb = Bs[buf];
#pragma unroll
        for (int k8 = 0; k8 < 16; k8 += 8) {
            wmma::fragment<wmma::matrix_a, 16, 16, 8, wmma::precision::tf32, wmma::row_major> a[2];
            wmma::fragment<wmma::matrix_b, 16, 16, 8, wmma::precision::tf32, wmma::row_major> b[4];
#pragma unroll
            for (int i = 0; i < 2; i++)
                wmma::load_matrix_sync(a[i], &Asb[(wm * 32 + i * 16) * TLDA + k8], TLDA);
#pragma unroll
            for (int j = 0; j < 4; j++)
                wmma::load_matrix_sync(b[j], &Bsb[k8 * TLDB + wn * 64 + j * 16], TLDB);
#pragma unroll
            for (int i = 0; i < 2; i++)
#pragma unroll
                for (int j = 0; j < 4; j++)
                    wmma::mma_sync(acc[i][j], a[i], b[j], acc[i][j]);
        }

        if (have_next) {
            int nb = buf ^ 1;
            float* ap = &As[nb][a_r * TLDA + a_c];
            ap[0] = wmma::__float_to_tf32(av0.x); ap[1] = wmma::__float_to_tf32(av0.y);
            ap[2] = wmma::__float_to_tf32(av0.z); ap[3] = wmma::__float_to_tf32(av0.w);
            ap[4] = wmma::__float_to_tf32(av1.x); ap[5] = wmma::__float_to_tf32(av1.y);
            ap[6] = wmma::__float_to_tf32(av1.z); ap[7] = wmma::__float_to_tf32(av1.w);
            float* bp = &Bs[nb][b_r * TLDB + b_c];
            bp[0] = wmma::__float_to_tf32(bv0.x); bp[1] = wmma::__float_to_tf32(bv0.y);
            bp[2] = wmma::__float_to_tf32(bv0.z); bp[3] = wmma::__float_to_tf32(bv0.w);
            bp[4] = wmma::__float_to_tf32(bv1.x); bp[5] = wmma::__float_to_tf32(bv1.y);
            bp[6] = wmma::__float_to_tf32(bv1.z); bp[7] = wmma::__float_to_tf32(bv1.w);
        }
        __syncthreads();
        buf ^= 1;
    }

    // ---- epilogue: per-warp staging, bias + relu, global store ----
    int er = lane >> 1;            // 0..15
    int ec = (lane & 1) << 3;      // 0 or 8
#pragma unroll
    for (int i = 0; i < 2; i++) {
#pragma unroll
        for (int j = 0; j < 4; j++) {
            wmma::store_matrix_sync(&stage[warp][0], acc[i][j], 20, wmma::mem_row_major);
            __syncwarp();
            int gcol = col0 + wn * 64 + j * 16 + ec;
            int grow = row0 + wm * 32 + i * 16 + er;
            float o[8];
#pragma unroll
            for (int q = 0; q < 8; q++) o[q] = stage[warp][er * 20 + ec + q];
            if (bias) {
                float4 bb0 = *reinterpret_cast<const float4*>(&bias[gcol]);
                float4 bb1 = *reinterpret_cast<const float4*>(&bias[gcol + 4]);
                o[0] += bb0.x; o[1] += bb0.y; o[2] += bb0.z; o[3] += bb0.w;
                o[4] += bb1.x; o[5] += bb1.y; o[6] += bb1.z; o[7] += bb1.w;
            }
            if (relu) {
#pragma unroll
                for (int q = 0; q < 8; q++) o[q] = o[q] > 0.f ? o[q] : 0.f;
            }
            if (grow < M) {
                *reinterpret_cast<float4*>(&C[(size_t)grow * 256 + gcol]) =
                    *reinterpret_cast<float4*>(&o[0]);
                *reinterpret_cast<float4*>(&C[(size_t)grow * 256 + gcol + 4]) =
                    *reinterpret_cast<float4*>(&o[4]);
            }
            __syncwarp();
        }
    }
}

// ---------------- launch ----------------
extern "C" void kernel_launch(void* const* d_in, const int* in_sizes, int n_in,
                              void* d_out, int out_size) {
    const float* x    = (const float*)d_in[0];
    const int*   ei   = (const int*)d_in[1];
    const float* Wn   = (const float*)d_in[2];
    const float* bn   = (const float*)d_in[3];
    const float* We   = (const float*)d_in[4];
    const float* be   = (const float*)d_in[5];
    const float* Ws1  = (const float*)d_in[6];
    const float* bs1  = (const float*)d_in[7];
    const float* Ws2  = (const float*)d_in[8];
    const float* bs2  = (const float*)d_in[9];
    const float* Wh1  = (const float*)d_in[10];
    const float* bh1  = (const float*)d_in[11];
    const float* Wh2  = (const float*)d_in[12];
    const float* bh2  = (const float*)d_in[13];

    const int H = in_sizes[3];            // 256
    const int F = in_sizes[2] / H;        // 256
    const int N = in_sizes[0] / F;
    const int E = in_sizes[1] / 2;
    const int WORDS = (N + 31) / 32;
    (void)n_in; (void)out_size;

    const int* row = ei;
    const int* col = ei + E;

    float* out1 = (float*)d_out;                       // node_tokens
    float* out2 = out1 + (size_t)N * 256;              // edge_tokens
    float* out3 = out2 + (size_t)E * 256;              // subgraph_tokens
    float* out4 = out3 + (size_t)N * 256;              // neighborhood_tokens

    float *pP, *pQ, *pNbr, *pF2, *pS1, *pT1;
    cudaGetSymbolAddress((void**)&pP,  g_P);
    cudaGetSymbolAddress((void**)&pQ,  g_Q);
    cudaGetSymbolAddress((void**)&pNbr, g_nbr);
    cudaGetSymbolAddress((void**)&pF2, g_f2);
    cudaGetSymbolAddress((void**)&pS1, g_S1);
    cudaGetSymbolAddress((void**)&pT1, g_T1);

    size_t f2_smem = (size_t)(F2_TR * 128) * sizeof(float) + (F2_MI * 6) * sizeof(unsigned);
    cudaFuncSetAttribute(feat2_kernel, cudaFuncAttributeMaxDynamicSharedMemorySize,
                         (int)f2_smem);

    dim3 gblk(256);
    int rt = (N + 127) / 128;

    // zero accumulating scratch
    zero_kernel<<<512, 256>>>(N, WORDS);

    // --- fused tokenizer GEMMs: out1 = x@Wn+bn, P = x@We_top+be, Q = x@We_bot ---
    {
        Job ja = {x, nullptr, nullptr, Wn, bn, out1, 1, 0};
        Job jb = {x, nullptr, nullptr, We, be, pP,   1, 0};
        Job jc = {x, nullptr, nullptr, We + (size_t)F * 256, nullptr, pQ, 1, 0};
        sgemm_kernel<<<dim3(2, rt, 3), gblk>>>(ja, jb, jc, N);
    }

    // graph structure
    int eb = (E + 255) / 256;
    edge_prep_kernel<<<eb, 256>>>(row, col, E, WORDS);
    scan_kernel<<<1, 256>>>(N);
    scatter_kernel<<<eb, 256>>>(row, col, E);

    // 1-hop mean + 2-hop reach bitsets
    hop1_kernel<<<N, 256>>>(out1, N, WORDS);

    // edge tokens
    long long etot = (long long)E * 64;
    int etb = (int)((etot + 255) / 256);
    edge_tok_kernel<<<etb, 256>>>(row, col, out2, E);

    // feat2 (2-hop unique mean)
    int f2grid = (N + F2_MI - 1) / F2_MI;
    feat2_kernel<<<dim3(f2grid, 2), 256, f2_smem>>>(out1, N, WORDS);

    // --- fused MLP layer 1 ---
    {
        Job ja = {out1, pNbr, nullptr, Ws1, bs1, pS1, 2, 1};
        Job jb = {out1, pNbr, pF2,     Wh1, bh1, pT1, 3, 1};
        sgemm_kernel<<<dim3(2, rt, 2), gblk>>>(ja, jb, ja, N);
    }

    // --- fused MLP layer 2 ---
    {
        Job ja = {pS1, nullptr, nullptr, Ws2, bs2, out3, 1, 0};
        Job jb = {pT1, nullptr, nullptr, Wh2, bh2, out4, 1, 0};
        sgemm_kernel<<<dim3(2, rt, 2), gblk>>>(ja, jb, ja, N);
    }
}

// round 8
// speedup vs baseline: 1.0643x; 1.0643x over previous
#include <cuda_runtime.h>
#include <cuda_bf16.h>
#include <mma.h>
#include <cstdint>

using namespace nvcuda;

// ================= static scratch (no allocs allowed) =================
#define MAXN 10240
#define MAXE 330240
#define MAXW 320   // ceil(MAXN/32)

__device__ float   g_P[MAXN * 256];
__device__ float   g_Q[MAXN * 256];
__device__ float   g_nbr[MAXN * 256];
__device__ float   g_f2[MAXN * 256];
__device__ float   g_S1[MAXN * 256];
__device__ float   g_T1[MAXN * 256];
__device__ unsigned g_AB[MAXN * MAXW];
__device__ unsigned g_RB[MAXN * MAXW];
__device__ int     g_rowptr[MAXN + 1];
__device__ int     g_cursor[MAXN];
__device__ int     g_degcnt[MAXN];
__device__ int     g_csrcol[MAXE];
__device__ float   g_cnt2[MAXN];
// pre-split bf16 weights, [k][n] row-major per job: 655360 bf16 each
__device__ __nv_bfloat16 g_Bh[655360];
__device__ __nv_bfloat16 g_Bl[655360];

// ================= prep: zero scratch + split weights to bf16 hi/lo =================
struct PrepJob { const float* W; int K; int boff; };

__global__ void prep_kernel(PrepJob p0, PrepJob p1, PrepJob p2, PrepJob p3,
                            PrepJob p4, PrepJob p5, PrepJob p6, int n, int words) {
    size_t gid = (size_t)blockIdx.x * blockDim.x + threadIdx.x;
    size_t stride = (size_t)gridDim.x * blockDim.x;
    size_t ztot = (size_t)n * words;
    for (size_t i = gid; i < ztot; i += stride) {
        g_AB[i] = 0u;
        if (i < (size_t)n) g_degcnt[i] = 0;
    }
    PrepJob jobs[7] = {p0, p1, p2, p3, p4, p5, p6};
    const int total = 655360;
    for (size_t e = gid; e < (size_t)total; e += stride) {
        int rem = (int)e, j = 0;
        while (rem >= 256 * jobs[j].K) { rem -= 256 * jobs[j].K; j++; }
        int nn = rem & 255;
        int k  = rem >> 8;
        float x = jobs[j].W[(size_t)k * 256 + nn];
        __nv_bfloat16 h = __float2bfloat16(x);
        __nv_bfloat16 l = __float2bfloat16(x - __bfloat162float(h));
        int dst = jobs[j].boff + k * 256 + nn;
        g_Bh[dst] = h;
        g_Bl[dst] = l;
    }
}

// ================= per-edge: degree count + adjacency bitset =================
__global__ void edge_prep_kernel(const int* __restrict__ row, const int* __restrict__ col,
                                 int E, int words) {
    int e = blockIdx.x * blockDim.x + threadIdx.x;
    if (e >= E) return;
    int r = row[e], c = col[e];
    atomicAdd(&g_degcnt[r], 1);
    atomicOr(&g_AB[(size_t)r * words + (c >> 5)], 1u << (c & 31));
}

// ================= scan (256 thr, chunked + warp scan) =================
__global__ void scan_kernel(int n) {
    __shared__ int sums[257];
    int t = threadIdx.x;
    int chunk = (n + 255) >> 8;
    int s0 = t * chunk; if (s0 > n) s0 = n;
    int s1 = s0 + chunk; if (s1 > n) s1 = n;
    int sum = 0;
    for (int i = s0; i < s1; i++) sum += g_degcnt[i];
    sums[t] = sum;
    __syncthreads();
    if (t < 32) {
        int vals[8];
        int g = 0;
#pragma unroll
        for (int k = 0; k < 8; k++) { vals[k] = sums[t * 8 + k]; g += vals[k]; }
        int inc = g;
#pragma unroll
        for (int off = 1; off < 32; off <<= 1) {
            int u = __shfl_up_sync(0xffffffffu, inc, off);
            if (t >= off) inc += u;
        }
        int exc = inc - g;
#pragma unroll
        for (int k = 0; k < 8; k++) { sums[t * 8 + k] = exc; exc += vals[k]; }
        if (t == 31) sums[256] = inc;
    }
    __syncthreads();
    int run = sums[t];
    for (int i = s0; i < s1; i++) {
        int v = g_degcnt[i];
        g_rowptr[i] = run; g_cursor[i] = run;
        run += v;
    }
    if (t == 0) g_rowptr[n] = sums[256];
}

// ================= CSR scatter =================
__global__ void scatter_kernel(const int* __restrict__ row, const int* __restrict__ col, int E) {
    int e = blockIdx.x * blockDim.x + threadIdx.x;
    if (e >= E) return;
    int r = row[e];
    int p = atomicAdd(&g_cursor[r], 1);
    g_csrcol[p] = col[e];
}

// ================= 1-hop: nbr_mean + reach bitset + cnt2 =================
__global__ void hop1_kernel(const float* __restrict__ NT, int n, int words) {
    int i = blockIdx.x;
    int t = threadIdx.x;
    int t2 = 256 + t;
    int s0 = g_rowptr[i], s1 = g_rowptr[i + 1];
    unsigned w0 = 0u, w1 = 0u;
    float acc = 0.f;
    for (int p = s0; p < s1; p++) {
        int j = g_csrcol[p];
        const unsigned* abr = &g_AB[(size_t)j * words];
        if (t < words)  w0 |= abr[t];
        if (t2 < words) w1 |= abr[t2];
        acc += NT[(size_t)j * 256 + t];
    }
    int wi = i >> 5;
    unsigned sb = 1u << (i & 31);
    if (wi == t)  w0 &= ~sb;
    if (wi == t2) w1 &= ~sb;
    if (t < words)  g_RB[(size_t)i * words + t]  = w0;
    if (t2 < words) g_RB[(size_t)i * words + t2] = w1;

    int deg = s1 - s0;
    float inv = deg > 0 ? 1.f / (float)deg : 0.f;
    g_nbr[(size_t)i * 256 + t] = acc * inv;

    __shared__ int red[256];
    red[t] = __popc(w0) + __popc(w1);
    __syncthreads();
    for (int off = 128; off > 0; off >>= 1) {
        if (t < off) red[t] += red[t + off];
        __syncthreads();
    }
    if (t == 0) g_cnt2[i] = (float)red[0];
}

// ================= edge tokens =================
__global__ void edge_tok_kernel(const int* __restrict__ row, const int* __restrict__ col,
                                float* __restrict__ out2, int E) {
    long long idx = (long long)blockIdx.x * blockDim.x + threadIdx.x;
    long long total = (long long)E * 64;
    if (idx >= total) return;
    int e = (int)(idx >> 6);
    int q = (int)(idx & 63);
    int r = row[e], c = col[e];
    float4 a = reinterpret_cast<const float4*>(g_P)[(size_t)r * 64 + q];
    float4 b = reinterpret_cast<const float4*>(g_Q)[(size_t)c * 64 + q];
    float4 o;
    o.x = a.x + b.x; o.y = a.y + b.y; o.z = a.z + b.z; o.w = a.w + b.w;
    reinterpret_cast<float4*>(out2)[idx] = o;
}

// ================= feat2: column-split bitset-masked row sum =================
#define F2_MI 64
#define F2_TR 192
__global__ __launch_bounds__(256, 2)
void feat2_kernel(const float* __restrict__ NT, int n, int words) {
    extern __shared__ float tile[];
    unsigned* smask = (unsigned*)(tile + F2_TR * 128);

    int t = threadIdx.x;
    int w = t >> 5;
    int l = t & 31;
    int h = blockIdx.y;
    int i0 = blockIdx.x * F2_MI;
    int cbase = h * 128 + l * 4;

    float acc[8][4];
#pragma unroll
    for (int k = 0; k < 8; k++) {
        acc[k][0] = 0.f; acc[k][1] = 0.f; acc[k][2] = 0.f; acc[k][3] = 0.f;
    }

    int ntiles = (words + 5) / 6;
    for (int tb = 0; tb < ntiles; tb++) {
        int k0 = tb * F2_TR;
        for (int v = t; v < F2_TR * 32; v += 256) {
            int r = v >> 5;
            int c = (v & 31) << 2;
            int kk = k0 + r;
            float4 val = make_float4(0.f, 0.f, 0.f, 0.f);
            if (kk < n)
                val = *reinterpret_cast<const float4*>(&NT[(size_t)kk * 256 + h * 128 + c]);
            *reinterpret_cast<float4*>(&tile[r * 128 + c]) = val;
        }
        for (int v = t; v < F2_MI * 6; v += 256) {
            int m = v / 6, wl = v % 6;
            int i = i0 + m;
            int wd = tb * 6 + wl;
            smask[v] = (i < n && wd < words) ? g_RB[(size_t)i * words + wd] : 0u;
        }
        __syncthreads();
#pragma unroll
        for (int k = 0; k < 8; k++) {
            int m = w * 8 + k;
#pragma unroll
            for (int wl = 0; wl < 6; wl++) {
                unsigned mask = smask[m * 6 + wl];
                while (mask) {
                    int b = __ffs(mask) - 1;
                    mask &= mask - 1;
                    const float4 v =
                        *reinterpret_cast<const float4*>(&tile[((wl << 5) + b) * 128 + l * 4]);
                    acc[k][0] += v.x; acc[k][1] += v.y;
                    acc[k][2] += v.z; acc[k][3] += v.w;
                }
            }
        }
        __syncthreads();
    }
#pragma unroll
    for (int k = 0; k < 8; k++) {
        int i = i0 + w * 8 + k;
        if (i < n) {
            float c = g_cnt2[i];
            float inv = c > 0.f ? 1.f / c : 0.f;
            float4 o;
            o.x = acc[k][0] * inv; o.y = acc[k][1] * inv;
            o.z = acc[k][2] * inv; o.w = acc[k][3] * inv;
            *reinterpret_cast<float4*>(&g_f2[(size_t)i * 256 + cbase]) = o;
        }
    }
}

// ================= GEMM v8: wmma bf16 hi/lo 3-pass, 128x128 tile =================
// C[M,256] = act( [A0|A1|A2][M,K] @ W[K,256] + bias ), K = nblk*256.
// A = Ah+Al, B = Bh+Bl (bf16 split); D = Ah*Bh + Ah*Bl + Al*Bh (fp32 acc).
// 8 warps, each owns 32x64 (2x4 m16n16k16 frags). K=64 chunk per sync stage.
struct GJob {
    const float* A0; const float* A1; const float* A2;
    const float* bias; float* C;
    int boff; int nblk; int relu;
};

// smem byte offsets (dynamic)
#define W8_AH 0
#define W8_AL 18432                 // 128*72*2
#define W8_BH 36864
#define W8_BL 54272                 // + 64*136*2
#define W8_ST 71680                 // stage: 8 warps * 320 floats
#define W8_TOTAL 81920

#define LDA 72
#define LDB 136

__global__ __launch_bounds__(256, 2)
void gemm_wmma(GJob j0, GJob j1, GJob j2, int M) {
    extern __shared__ __align__(32) char smem[];
    __nv_bfloat16* Ah = (__nv_bfloat16*)(smem + W8_AH);
    __nv_bfloat16* Al = (__nv_bfloat16*)(smem + W8_AL);
    __nv_bfloat16* Bh = (__nv_bfloat16*)(smem + W8_BH);
    __nv_bfloat16* Bl = (__nv_bfloat16*)(smem + W8_BL);
    float* stage = (float*)(smem + W8_ST);

    GJob jb = (blockIdx.z == 0) ? j0 : ((blockIdx.z == 1) ? j1 : j2);
    int tid  = threadIdx.x;
    int warp = tid >> 5;
    int lane = tid & 31;
    int wm = warp >> 1;          // 0..3
    int wn = warp & 1;           // 0..1
    int row0 = blockIdx.y * 128;
    int col0 = blockIdx.x * 128;

    wmma::fragment<wmma::accumulator, 16, 16, 16, float> acc[2][4];
#pragma unroll
    for (int i = 0; i < 2; i++)
#pragma unroll
        for (int j = 0; j < 4; j++) wmma::fill_fragment(acc[i][j], 0.f);

    int a_r = tid >> 1;              // 0..127 (A row)
    int a_c = (tid & 1) << 5;        // 0 or 32 (A col group, 8 float4 = 32 k)
    int gar = row0 + a_r;

    int nchunks = jb.nblk * 4;       // 64 K per chunk
    for (int ch = 0; ch < nchunks; ch++) {
        int kt = ch * 64;
        const float* Ap = (kt < 256) ? jb.A0 : ((kt < 512) ? jb.A1 : jb.A2);
        int ko = kt & 255;

        // ---- stage A: 128 rows x 64 k, fp32 -> bf16 hi/lo ----
#pragma unroll
        for (int u = 0; u < 8; u++) {
            int c = a_c + u * 4;     // k within chunk
            float4 x = make_float4(0.f, 0.f, 0.f, 0.f);
            if (gar < M) x = *reinterpret_cast<const float4*>(&Ap[(size_t)gar * 256 + ko + c]);
            __nv_bfloat16 h0 = __float2bfloat16(x.x);
            __nv_bfloat16 h1 = __float2bfloat16(x.y);
            __nv_bfloat16 h2 = __float2bfloat16(x.z);
            __nv_bfloat16 h3 = __float2bfloat16(x.w);
            __nv_bfloat16 l0 = __float2bfloat16(x.x - __bfloat162float(h0));
            __nv_bfloat16 l1 = __float2bfloat16(x.y - __bfloat162float(h1));
            __nv_bfloat16 l2 = __float2bfloat16(x.z - __bfloat162float(h2));
            __nv_bfloat16 l3 = __float2bfloat16(x.w - __bfloat162float(h3));
            uint32_t hA = (uint32_t)__bfloat16_as_ushort(h0) | ((uint32_t)__bfloat16_as_ushort(h1) << 16);
            uint32_t hB = (uint32_t)__bfloat16_as_ushort(h2) | ((uint32_t)__bfloat16_as_ushort(h3) << 16);
            uint32_t lA = (uint32_t)__bfloat16_as_ushort(l0) | ((uint32_t)__bfloat16_as_ushort(l1) << 16);
            uint32_t lB = (uint32_t)__bfloat16_as_ushort(l2) | ((uint32_t)__bfloat16_as_ushort(l3) << 16);
            *reinterpret_cast<uint2*>(&Ah[a_r * LDA + c]) = make_uint2(hA, hB);
            *reinterpret_cast<uint2*>(&Al[a_r * LDA + c]) = make_uint2(lA, lB);
        }
        // ---- stage B: 64 k x 128 n, pre-split bf16 straight copy ----
        {
            int boff = jb.boff + kt * 256 + col0;
#pragma unroll
            for (int u = 0; u < 4; u++) {
                int v = tid + u * 256;       // 0..1023
                int k = v >> 4;              // 0..63
                int n8 = (v & 15) << 3;      // 0..120
                *reinterpret_cast<uint4*>(&Bh[k * LDB + n8]) =
                    *reinterpret_cast<const uint4*>(&g_Bh[boff + k * 256 + n8]);
                *reinterpret_cast<uint4*>(&Bl[k * LDB + n8]) =
                    *reinterpret_cast<const uint4*>(&g_Bl[boff + k * 256 + n8]);
            }
        }
        __syncthreads();

        // ---- compute: 4 k16 steps ----
#pragma unroll
        for (int ks = 0; ks < 4; ks++) {
            wmma::fragment<wmma::matrix_a, 16, 16, 16, __nv_bfloat16, wmma::row_major> ah[2], al[2];
#pragma unroll
            for (int i = 0; i < 2; i++) {
                wmma::load_matrix_sync(ah[i], &Ah[(wm * 32 + i * 16) * LDA + ks * 16], LDA);
                wmma::load_matrix_sync(al[i], &Al[(wm * 32 + i * 16) * LDA + ks * 16], LDA);
            }
#pragma unroll
            for (int j = 0; j < 4; j++) {
                wmma::fragment<wmma::matrix_b, 16, 16, 16, __nv_bfloat16, wmma::row_major> bh, bl;
                wmma::load_matrix_sync(bh, &Bh[(ks * 16) * LDB + wn * 64 + j * 16], LDB);
                wmma::load_matrix_sync(bl, &Bl[(ks * 16) * LDB + wn * 64 + j * 16], LDB);
#pragma unroll
                for (int i = 0; i < 2; i++) {
                    wmma::mma_sync(acc[i][j], ah[i], bh, acc[i][j]);
                    wmma::mma_sync(acc[i][j], ah[i], bl, acc[i][j]);
                    wmma::mma_sync(acc[i][j], al[i], bh, acc[i][j]);
                }
            }
        }
        __syncthreads();
    }

    // ---- epilogue: per-warp stage, bias + relu, global store ----
    int er = lane >> 1;
    int ec = (lane & 1) << 3;
    float* st = &stage[warp * 320];
#pragma unroll
    for (int i = 0; i < 2; i++) {
#pragma unroll
        for (int j = 0; j < 4; j++) {
            wmma::store_matrix_sync(st, acc[i][j], 20, wmma::mem_row_major);
            __syncwarp();
            int gcol = col0 + wn * 64 + j * 16 + ec;
            int grow = row0 + wm * 32 + i * 16 + er;
            float o[8];
#pragma unroll
            for (int q = 0; q < 8; q++) o[q] = st[er * 20 + ec + q];
            if (jb.bias) {
                float4 b0 = *reinterpret_cast<const float4*>(&jb.bias[gcol]);
                float4 b1 = *reinterpret_cast<const float4*>(&jb.bias[gcol + 4]);
                o[0] += b0.x; o[1] += b0.y; o[2] += b0.z; o[3] += b0.w;
                o[4] += b1.x; o[5] += b1.y; o[6] += b1.z; o[7] += b1.w;
            }
            if (jb.relu) {
#pragma unroll
                for (int q = 0; q < 8; q++) o[q] = o[q] > 0.f ? o[q] : 0.f;
            }
            if (grow < M) {
                *reinterpret_cast<float4*>(&jb.C[(size_t)grow * 256 + gcol]) =
                    *reinterpret_cast<float4*>(&o[0]);
                *reinterpret_cast<float4*>(&jb.C[(size_t)grow * 256 + gcol + 4]) =
                    *reinterpret_cast<float4*>(&o[4]);
            }
            __syncwarp();
        }
    }
}

// ================= launch =================
extern "C" void kernel_launch(void* const* d_in, const int* in_sizes, int n_in,
                              void* d_out, int out_size) {
    const float* x    = (const float*)d_in[0];
    const int*   ei   = (const int*)d_in[1];
    const float* Wn   = (const float*)d_in[2];
    const float* bn   = (const float*)d_in[3];
    const float* We   = (const float*)d_in[4];
    const float* be   = (const float*)d_in[5];
    const float* Ws1  = (const float*)d_in[6];
    const float* bs1  = (const float*)d_in[7];
    const float* Ws2  = (const float*)d_in[8];
    const float* bs2  = (const float*)d_in[9];
    const float* Wh1  = (const float*)d_in[10];
    const float* bh1  = (const float*)d_in[11];
    const float* Wh2  = (const float*)d_in[12];
    const float* bh2  = (const float*)d_in[13];

    const int H = in_sizes[3];            // 256
    const int F = in_sizes[2] / H;        // 256
    const int N = in_sizes[0] / F;
    const int E = in_sizes[1] / 2;
    const int WORDS = (N + 31) / 32;
    (void)n_in; (void)out_size;

    const int* row = ei;
    const int* col = ei + E;

    float* out1 = (float*)d_out;                       // node_tokens
    float* out2 = out1 + (size_t)N * 256;              // edge_tokens
    float* out3 = out2 + (size_t)E * 256;              // subgraph_tokens
    float* out4 = out3 + (size_t)N * 256;              // neighborhood_tokens

    float *pP, *pQ, *pNbr, *pF2, *pS1, *pT1;
    cudaGetSymbolAddress((void**)&pP,  g_P);
    cudaGetSymbolAddress((void**)&pQ,  g_Q);
    cudaGetSymbolAddress((void**)&pNbr, g_nbr);
    cudaGetSymbolAddress((void**)&pF2, g_f2);
    cudaGetSymbolAddress((void**)&pS1, g_S1);
    cudaGetSymbolAddress((void**)&pT1, g_T1);

    size_t f2_smem = (size_t)(F2_TR * 128) * sizeof(float) + (F2_MI * 6) * sizeof(unsigned);
    cudaFuncSetAttribute(feat2_kernel, cudaFuncAttributeMaxDynamicSharedMemorySize,
                         (int)f2_smem);
    cudaFuncSetAttribute(gemm_wmma, cudaFuncAttributeMaxDynamicSharedMemorySize, W8_TOTAL);

    int mt = (N + 127) / 128;

    // bf16 weight offsets: Wn, WeTop, WeBot, Ws1, Ws2, Wh1, Wh2
    const int BO_WN  = 0;
    const int BO_WET = 65536;
    const int BO_WEB = 131072;
    const int BO_WS1 = 196608;
    const int BO_WS2 = 327680;
    const int BO_WH1 = 393216;
    const int BO_WH2 = 589824;

    // (1) prep: zero AB/degcnt + split all weights to bf16 hi/lo
    {
        PrepJob p0 = {Wn, 256, BO_WN};
        PrepJob p1 = {We, 256, BO_WET};
        PrepJob p2 = {We + (size_t)256 * 256, 256, BO_WEB};
        PrepJob p3 = {Ws1, 512, BO_WS1};
        PrepJob p4 = {Ws2, 256, BO_WS2};
        PrepJob p5 = {Wh1, 768, BO_WH1};
        PrepJob p6 = {Wh2, 256, BO_WH2};
        prep_kernel<<<512, 256>>>(p0, p1, p2, p3, p4, p5, p6, N, WORDS);
    }

    // (2) edge_prep, (3) scan  — graph structure, independent of GEMMs
    int eb = (E + 255) / 256;
    edge_prep_kernel<<<eb, 256>>>(row, col, E, WORDS);
    scan_kernel<<<1, 256>>>(N);

    // (4) fused tokenizer GEMMs  <- profiled slot
    {
        GJob ja = {x, nullptr, nullptr, bn, out1, BO_WN, 1, 0};
        GJob jb = {x, nullptr, nullptr, be, pP,  BO_WET, 1, 0};
        GJob jc = {x, nullptr, nullptr, nullptr, pQ, BO_WEB, 1, 0};
        gemm_wmma<<<dim3(2, mt, 3), 256, W8_TOTAL>>>(ja, jb, jc, N);
    }

    // (5) scatter, (6) hop1, (7) edge_tok, (8) feat2
    scatter_kernel<<<eb, 256>>>(row, col, E);
    hop1_kernel<<<N, 256>>>(out1, N, WORDS);
    {
        long long etot = (long long)E * 64;
        int etb = (int)((etot + 255) / 256);
        edge_tok_kernel<<<etb, 256>>>(row, col, out2, E);
    }
    int f2grid = (N + F2_MI - 1) / F2_MI;
    feat2_kernel<<<dim3(f2grid, 2), 256, f2_smem>>>(out1, N, WORDS);

    // (9) MLP layer 1: S1 = relu([out1|nbr]@Ws1+bs1), T1 = relu([out1|nbr|f2]@Wh1+bh1)
    {
        GJob ja = {out1, pNbr, nullptr, bs1, pS1, BO_WS1, 2, 1};
        GJob jb = {out1, pNbr, pF2,     bh1, pT1, BO_WH1, 3, 1};
        gemm_wmma<<<dim3(2, mt, 2), 256, W8_TOTAL>>>(ja, jb, ja, N);
    }
    // (10) MLP layer 2: out3 = S1@Ws2+bs2, out4 = T1@Wh2+bh2
    {
        GJob ja = {pS1, nullptr, nullptr, bs2, out3, BO_WS2, 1, 0};
        GJob jb = {pT1, nullptr, nullptr, bh2, out4, BO_WH2, 1, 0};
        gemm_wmma<<<dim3(2, mt, 2), 256, W8_TOTAL>>>(ja, jb, ja, N);
    }
}

// round 9
// speedup vs baseline: 1.2150x; 1.1416x over previous
#include <cuda_runtime.h>
#include <cuda_bf16.h>
#include <mma.h>
#include <cstdint>

using namespace nvcuda;

// ================= static scratch (no allocs allowed) =================
#define MAXN 10240
#define MAXE 330240
#define MAXW 320   // ceil(MAXN/32)

__device__ float   g_P[MAXN * 256];
__device__ float   g_Q[MAXN * 256];
__device__ float   g_nbr[MAXN * 256];
__device__ float   g_f2[MAXN * 256];
__device__ float   g_S1[MAXN * 256];
__device__ float   g_T1[MAXN * 256];
__device__ unsigned g_AB[MAXN * MAXW];
__device__ unsigned g_RB[MAXN * MAXW];
__device__ int     g_rowptr[MAXN + 1];
__device__ int     g_cursor[MAXN];
__device__ int     g_degcnt[MAXN];
__device__ int     g_csrcol[MAXE];
__device__ float   g_cnt2[MAXN];
// pre-split bf16 weights, [k][n] row-major per job: 655360 bf16 each
__device__ __nv_bfloat16 g_Bh[655360];
__device__ __nv_bfloat16 g_Bl[655360];
// bf16 copy of node_tokens for feat2
__device__ __nv_bfloat16 g_NTb[MAXN * 256];

// ================= small ptx helpers =================
__device__ __forceinline__ uint32_t smem_u32(const void* p) {
    uint32_t a;
    asm("{ .reg .u64 t; cvta.to.shared.u64 t, %1; cvt.u32.u64 %0, t; }" : "=r"(a) : "l"(p));
    return a;
}
#define CP_COMMIT() asm volatile("cp.async.commit_group;" ::: "memory")
#define CP_WAIT1()  asm volatile("cp.async.wait_group 1;" ::: "memory")
#define CP_WAIT0()  asm volatile("cp.async.wait_group 0;" ::: "memory")

// ================= prep: zero scratch + split weights to bf16 hi/lo =================
struct PrepJob { const float* W; int K; int boff; };

__global__ void prep_kernel(PrepJob p0, PrepJob p1, PrepJob p2, PrepJob p3,
                            PrepJob p4, PrepJob p5, PrepJob p6, int n, int words) {
    size_t gid = (size_t)blockIdx.x * blockDim.x + threadIdx.x;
    size_t stride = (size_t)gridDim.x * blockDim.x;
    size_t ztot = (size_t)n * words;
    for (size_t i = gid; i < ztot; i += stride) {
        g_AB[i] = 0u;
        if (i < (size_t)n) g_degcnt[i] = 0;
    }
    PrepJob jobs[7] = {p0, p1, p2, p3, p4, p5, p6};
    const int total = 655360;
    for (size_t e = gid; e < (size_t)total; e += stride) {
        int rem = (int)e, j = 0;
        while (rem >= 256 * jobs[j].K) { rem -= 256 * jobs[j].K; j++; }
        int nn = rem & 255;
        int k  = rem >> 8;
        float x = jobs[j].W[(size_t)k * 256 + nn];
        __nv_bfloat16 h = __float2bfloat16(x);
        __nv_bfloat16 l = __float2bfloat16(x - __bfloat162float(h));
        int dst = jobs[j].boff + k * 256 + nn;
        g_Bh[dst] = h;
        g_Bl[dst] = l;
    }
}

// ================= node_tokens -> bf16 copy =================
__global__ void nt2bf_kernel(const float* __restrict__ NT, int total4) {
    int idx = blockIdx.x * blockDim.x + threadIdx.x;
    if (idx >= total4) return;
    float4 v = reinterpret_cast<const float4*>(NT)[idx];
    __nv_bfloat162 a = __floats2bfloat162_rn(v.x, v.y);
    __nv_bfloat162 b = __floats2bfloat162_rn(v.z, v.w);
    uint2 o;
    o.x = *reinterpret_cast<uint32_t*>(&a);
    o.y = *reinterpret_cast<uint32_t*>(&b);
    reinterpret_cast<uint2*>(g_NTb)[idx] = o;
}

// ================= per-edge: degree count + adjacency bitset =================
__global__ void edge_prep_kernel(const int* __restrict__ row, const int* __restrict__ col,
                                 int E, int words) {
    int e = blockIdx.x * blockDim.x + threadIdx.x;
    if (e >= E) return;
    int r = row[e], c = col[e];
    atomicAdd(&g_degcnt[r], 1);
    atomicOr(&g_AB[(size_t)r * words + (c >> 5)], 1u << (c & 31));
}

// ================= scan (256 thr, chunked + warp scan) =================
__global__ void scan_kernel(int n) {
    __shared__ int sums[257];
    int t = threadIdx.x;
    int chunk = (n + 255) >> 8;
    int s0 = t * chunk; if (s0 > n) s0 = n;
    int s1 = s0 + chunk; if (s1 > n) s1 = n;
    int sum = 0;
    for (int i = s0; i < s1; i++) sum += g_degcnt[i];
    sums[t] = sum;
    __syncthreads();
    if (t < 32) {
        int vals[8];
        int g = 0;
#pragma unroll
        for (int k = 0; k < 8; k++) { vals[k] = sums[t * 8 + k]; g += vals[k]; }
        int inc = g;
#pragma unroll
        for (int off = 1; off < 32; off <<= 1) {
            int u = __shfl_up_sync(0xffffffffu, inc, off);
            if (t >= off) inc += u;
        }
        int exc = inc - g;
#pragma unroll
        for (int k = 0; k < 8; k++) { sums[t * 8 + k] = exc; exc += vals[k]; }
        if (t == 31) sums[256] = inc;
    }
    __syncthreads();
    int run = sums[t];
    for (int i = s0; i < s1; i++) {
        int v = g_degcnt[i];
        g_rowptr[i] = run; g_cursor[i] = run;
        run += v;
    }
    if (t == 0) g_rowptr[n] = sums[256];
}

// ================= CSR scatter =================
__global__ void scatter_kernel(const int* __restrict__ row, const int* __restrict__ col, int E) {
    int e = blockIdx.x * blockDim.x + threadIdx.x;
    if (e >= E) return;
    int r = row[e];
    int p = atomicAdd(&g_cursor[r], 1);
    g_csrcol[p] = col[e];
}

// ================= 1-hop: nbr_mean + reach bitset + cnt2 =================
__global__ void hop1_kernel(const float* __restrict__ NT, int n, int words) {
    int i = blockIdx.x;
    int t = threadIdx.x;
    int t2 = 256 + t;
    int s0 = g_rowptr[i], s1 = g_rowptr[i + 1];
    unsigned w0 = 0u, w1 = 0u;
    float acc = 0.f;
    for (int p = s0; p < s1; p++) {
        int j = g_csrcol[p];
        const unsigned* abr = &g_AB[(size_t)j * words];
        if (t < words)  w0 |= abr[t];
        if (t2 < words) w1 |= abr[t2];
        acc += NT[(size_t)j * 256 + t];
    }
    int wi = i >> 5;
    unsigned sb = 1u << (i & 31);
    if (wi == t)  w0 &= ~sb;
    if (wi == t2) w1 &= ~sb;
    if (t < words)  g_RB[(size_t)i * words + t]  = w0;
    if (t2 < words) g_RB[(size_t)i * words + t2] = w1;

    int deg = s1 - s0;
    float inv = deg > 0 ? 1.f / (float)deg : 0.f;
    g_nbr[(size_t)i * 256 + t] = acc * inv;

    __shared__ int red[256];
    red[t] = __popc(w0) + __popc(w1);
    __syncthreads();
    for (int off = 128; off > 0; off >>= 1) {
        if (t < off) red[t] += red[t + off];
        __syncthreads();
    }
    if (t == 0) g_cnt2[i] = (float)red[0];
}

// ================= edge tokens =================
__global__ void edge_tok_kernel(const int* __restrict__ row, const int* __restrict__ col,
                                float* __restrict__ out2, int E) {
    long long idx = (long long)blockIdx.x * blockDim.x + threadIdx.x;
    long long total = (long long)E * 64;
    if (idx >= total) return;
    int e = (int)(idx >> 6);
    int q = (int)(idx & 63);
    int r = row[e], c = col[e];
    float4 a = reinterpret_cast<const float4*>(g_P)[(size_t)r * 64 + q];
    float4 b = reinterpret_cast<const float4*>(g_Q)[(size_t)c * 64 + q];
    float4 o;
    o.x = a.x + b.x; o.y = a.y + b.y; o.z = a.z + b.z; o.w = a.w + b.w;
    reinterpret_cast<float4*>(out2)[idx] = o;
}

// ================= feat2 v4: bf16 tile + cp.async double-buffer =================
// grid (ceil(n/64), 2): 64 nodes x 128-col half per CTA. Tile = 192 bf16 rows.
// Double-buffered tile+mask loads via cp.async overlap L2 with the bit loop.
#define F2_MI 64
#define F2_TR 192
#define F2_TILE_B 49152           // 192*128*2 bytes per buffer
#define F2_MASK_OFF 98304         // after 2 tile buffers
#define F2_SMEM_TOTAL (98304 + 2 * 1536)

__global__ __launch_bounds__(256, 2)
void feat2_kernel(int n, int words) {
    extern __shared__ char fsm[];
    uint32_t sbase = smem_u32(fsm);

    int t = threadIdx.x;
    int w = t >> 5;
    int l = t & 31;
    int h = blockIdx.y;
    int i0 = blockIdx.x * F2_MI;
    int cbase = h * 128 + l * 4;
    int ntiles = (words + 5) / 6;

    const __nv_bfloat16* NTb = g_NTb;
    const unsigned* RB = g_RB;

    float acc[8][4];
#pragma unroll
    for (int k = 0; k < 8; k++) {
        acc[k][0] = 0.f; acc[k][1] = 0.f; acc[k][2] = 0.f; acc[k][3] = 0.f;
    }

    // ---- async tile+mask issue for window tb into buffer buf ----
    auto issue = [&](int tb, int buf) {
        int k0 = tb * F2_TR;
        // tile: 192 rows x 256B (128 bf16) = 3072 x 16B ops, 12 per thread
#pragma unroll
        for (int u = 0; u < 12; u++) {
            int v = t + u * 256;
            int r = v >> 4;
            int c16 = v & 15;
            int kk = k0 + r;
            uint32_t dst = sbase + buf * F2_TILE_B + r * 256 + c16 * 16;
            const char* src;
            int sz;
            if (kk < n) {
                src = (const char*)&NTb[(size_t)kk * 256 + h * 128] + c16 * 16;
                sz = 16;
            } else {
                src = (const char*)&NTb[0];
                sz = 0;
            }
            asm volatile("cp.async.cg.shared.global [%0], [%1], 16, %2;"
                         :: "r"(dst), "l"(src), "r"(sz));
        }
        // masks: 64 nodes x 6 words = 384 x 4B ops
        for (int v = t; v < F2_MI * 6; v += 256) {
            int m = v / 6, wl = v % 6;
            int i = i0 + m;
            int wd = tb * 6 + wl;
            uint32_t dst = sbase + F2_MASK_OFF + buf * 1536 + v * 4;
            const char* src;
            int sz;
            if (i < n && wd < words) {
                src = (const char*)&RB[(size_t)i * words + wd];
                sz = 4;
            } else {
                src = (const char*)&RB[0];
                sz = 0;
            }
            asm volatile("cp.async.ca.shared.global [%0], [%1], 4, %2;"
                         :: "r"(dst), "l"(src), "r"(sz));
        }
        CP_COMMIT();
    };

    issue(0, 0);
    for (int tb = 0; tb < ntiles; tb++) {
        int buf = tb & 1;
        if (tb + 1 < ntiles) { issue(tb + 1, buf ^ 1); CP_WAIT1(); }
        else                 { CP_WAIT0(); }
        __syncthreads();

        const __nv_bfloat16* tile = (const __nv_bfloat16*)(fsm + buf * F2_TILE_B);
        const unsigned* smask = (const unsigned*)(fsm + F2_MASK_OFF + buf * 1536);
#pragma unroll
        for (int k = 0; k < 8; k++) {
            int m = w * 8 + k;
#pragma unroll
            for (int wl = 0; wl < 6; wl++) {
                unsigned mask = smask[m * 6 + wl];
                while (mask) {
                    int b = __ffs(mask) - 1;
                    mask &= mask - 1;
                    uint2 v2 = *reinterpret_cast<const uint2*>(
                        &tile[((wl << 5) + b) * 128 + l * 4]);
                    __nv_bfloat162 p0 = *reinterpret_cast<__nv_bfloat162*>(&v2.x);
                    __nv_bfloat162 p1 = *reinterpret_cast<__nv_bfloat162*>(&v2.y);
                    float2 f0 = __bfloat1622float2(p0);
                    float2 f1 = __bfloat1622float2(p1);
                    acc[k][0] += f0.x; acc[k][1] += f0.y;
                    acc[k][2] += f1.x; acc[k][3] += f1.y;
                }
            }
        }
        __syncthreads();   // protect buf before it is refilled
    }

#pragma unroll
    for (int k = 0; k < 8; k++) {
        int i = i0 + w * 8 + k;
        if (i < n) {
            float c = g_cnt2[i];
            float inv = c > 0.f ? 1.f / c : 0.f;
            float4 o;
            o.x = acc[k][0] * inv; o.y = acc[k][1] * inv;
            o.z = acc[k][2] * inv; o.w = acc[k][3] * inv;
            *reinterpret_cast<float4*>(&g_f2[(size_t)i * 256 + cbase]) = o;
        }
    }
}

// ================= GEMM: wmma bf16 hi/lo 3-pass, 128x128 tile (r8, proven) =================
struct GJob {
    const float* A0; const float* A1; const float* A2;
    const float* bias; float* C;
    int boff; int nblk; int relu;
};

#define W8_AH 0
#define W8_AL 18432
#define W8_BH 36864
#define W8_BL 54272
#define W8_ST 71680
#define W8_TOTAL 81920

#define LDA 72
#define LDB 136

__global__ __launch_bounds__(256, 2)
void gemm_wmma(GJob j0, GJob j1, GJob j2, int M) {
    extern __shared__ __align__(32) char smem[];
    __nv_bfloat16* Ah = (__nv_bfloat16*)(smem + W8_AH);
    __nv_bfloat16* Al = (__nv_bfloat16*)(smem + W8_AL);
    __nv_bfloat16* Bh = (__nv_bfloat16*)(smem + W8_BH);
    __nv_bfloat16* Bl = (__nv_bfloat16*)(smem + W8_BL);
    float* stage = (float*)(smem + W8_ST);

    GJob jb = (blockIdx.z == 0) ? j0 : ((blockIdx.z == 1) ? j1 : j2);
    int tid  = threadIdx.x;
    int warp = tid >> 5;
    int lane = tid & 31;
    int wm = warp >> 1;
    int wn = warp & 1;
    int row0 = blockIdx.y * 128;
    int col0 = blockIdx.x * 128;

    wmma::fragment<wmma::accumulator, 16, 16, 16, float> acc[2][4];
#pragma unroll
    for (int i = 0; i < 2; i++)
#pragma unroll
        for (int j = 0; j < 4; j++) wmma::fill_fragment(acc[i][j], 0.f);

    int a_r = tid >> 1;
    int a_c = (tid & 1) << 5;
    int gar = row0 + a_r;

    int nchunks = jb.nblk * 4;
    for (int ch = 0; ch < nchunks; ch++) {
        int kt = ch * 64;
        const float* Ap = (kt < 256) ? jb.A0 : ((kt < 512) ? jb.A1 : jb.A2);
        int ko = kt & 255;

#pragma unroll
        for (int u = 0; u < 8; u++) {
            int c = a_c + u * 4;
            float4 x = make_float4(0.f, 0.f, 0.f, 0.f);
            if (gar < M) x = *reinterpret_cast<const float4*>(&Ap[(size_t)gar * 256 + ko + c]);
            __nv_bfloat16 h0 = __float2bfloat16(x.x);
            __nv_bfloat16 h1 = __float2bfloat16(x.y);
            __nv_bfloat16 h2 = __float2bfloat16(x.z);
            __nv_bfloat16 h3 = __float2bfloat16(x.w);
            __nv_bfloat16 l0 = __float2bfloat16(x.x - __bfloat162float(h0));
            __nv_bfloat16 l1 = __float2bfloat16(x.y - __bfloat162float(h1));
            __nv_bfloat16 l2 = __float2bfloat16(x.z - __bfloat162float(h2));
            __nv_bfloat16 l3 = __float2bfloat16(x.w - __bfloat162float(h3));
            uint32_t hA = (uint32_t)__bfloat16_as_ushort(h0) | ((uint32_t)__bfloat16_as_ushort(h1) << 16);
            uint32_t hB = (uint32_t)__bfloat16_as_ushort(h2) | ((uint32_t)__bfloat16_as_ushort(h3) << 16);
            uint32_t lA = (uint32_t)__bfloat16_as_ushort(l0) | ((uint32_t)__bfloat16_as_ushort(l1) << 16);
            uint32_t lB = (uint32_t)__bfloat16_as_ushort(l2) | ((uint32_t)__bfloat16_as_ushort(l3) << 16);
            *reinterpret_cast<uint2*>(&Ah[a_r * LDA + c]) = make_uint2(hA, hB);
            *reinterpret_cast<uint2*>(&Al[a_r * LDA + c]) = make_uint2(lA, lB);
        }
        {
            int boff = jb.boff + kt * 256 + col0;
#pragma unroll
            for (int u = 0; u < 4; u++) {
                int v = tid + u * 256;
                int k = v >> 4;
                int n8 = (v & 15) << 3;
                *reinterpret_cast<uint4*>(&Bh[k * LDB + n8]) =
                    *reinterpret_cast<const uint4*>(&g_Bh[boff + k * 256 + n8]);
                *reinterpret_cast<uint4*>(&Bl[k * LDB + n8]) =
                    *reinterpret_cast<const uint4*>(&g_Bl[boff + k * 256 + n8]);
            }
        }
        __syncthreads();

#pragma unroll
        for (int ks = 0; ks < 4; ks++) {
            wmma::fragment<wmma::matrix_a, 16, 16, 16, __nv_bfloat16, wmma::row_major> ah[2], al[2];
#pragma unroll
            for (int i = 0; i < 2; i++) {
                wmma::load_matrix_sync(ah[i], &Ah[(wm * 32 + i * 16) * LDA + ks * 16], LDA);
                wmma::load_matrix_sync(al[i], &Al[(wm * 32 + i * 16) * LDA + ks * 16], LDA);
            }
#pragma unroll
            for (int j = 0; j < 4; j++) {
                wmma::fragment<wmma::matrix_b, 16, 16, 16, __nv_bfloat16, wmma::row_major> bh, bl;
                wmma::load_matrix_sync(bh, &Bh[(ks * 16) * LDB + wn * 64 + j * 16], LDB);
                wmma::load_matrix_sync(bl, &Bl[(ks * 16) * LDB + wn * 64 + j * 16], LDB);
#pragma unroll
                for (int i = 0; i < 2; i++) {
                    wmma::mma_sync(acc[i][j], ah[i], bh, acc[i][j]);
                    wmma::mma_sync(acc[i][j], ah[i], bl, acc[i][j]);
                    wmma::mma_sync(acc[i][j], al[i], bh, acc[i][j]);
                }
            }
        }
        __syncthreads();
    }

    int er = lane >> 1;
    int ec = (lane & 1) << 3;
    float* st = &stage[warp * 320];
#pragma unroll
    for (int i = 0; i < 2; i++) {
#pragma unroll
        for (int j = 0; j < 4; j++) {
            wmma::store_matrix_sync(st, acc[i][j], 20, wmma::mem_row_major);
            __syncwarp();
            int gcol = col0 + wn * 64 + j * 16 + ec;
            int grow = row0 + wm * 32 + i * 16 + er;
            float o[8];
#pragma unroll
            for (int q = 0; q < 8; q++) o[q] = st[er * 20 + ec + q];
            if (jb.bias) {
                float4 b0 = *reinterpret_cast<const float4*>(&jb.bias[gcol]);
                float4 b1 = *reinterpret_cast<const float4*>(&jb.bias[gcol + 4]);
                o[0] += b0.x; o[1] += b0.y; o[2] += b0.z; o[3] += b0.w;
                o[4] += b1.x; o[5] += b1.y; o[6] += b1.z; o[7] += b1.w;
            }
            if (jb.relu) {
#pragma unroll
                for (int q = 0; q < 8; q++) o[q] = o[q] > 0.f ? o[q] : 0.f;
            }
            if (grow < M) {
                *reinterpret_cast<float4*>(&jb.C[(size_t)grow * 256 + gcol]) =
                    *reinterpret_cast<float4*>(&o[0]);
                *reinterpret_cast<float4*>(&jb.C[(size_t)grow * 256 + gcol + 4]) =
                    *reinterpret_cast<float4*>(&o[4]);
            }
            __syncwarp();
        }
    }
}

// ================= launch =================
extern "C" void kernel_launch(void* const* d_in, const int* in_sizes, int n_in,
                              void* d_out, int out_size) {
    const float* x    = (const float*)d_in[0];
    const int*   ei   = (const int*)d_in[1];
    const float* Wn   = (const float*)d_in[2];
    const float* bn   = (const float*)d_in[3];
    const float* We   = (const float*)d_in[4];
    const float* be   = (const float*)d_in[5];
    const float* Ws1  = (const float*)d_in[6];
    const float* bs1  = (const float*)d_in[7];
    const float* Ws2  = (const float*)d_in[8];
    const float* bs2  = (const float*)d_in[9];
    const float* Wh1  = (const float*)d_in[10];
    const float* bh1  = (const float*)d_in[11];
    const float* Wh2  = (const float*)d_in[12];
    const float* bh2  = (const float*)d_in[13];

    const int H = in_sizes[3];            // 256
    const int F = in_sizes[2] / H;        // 256
    const int N = in_sizes[0] / F;
    const int E = in_sizes[1] / 2;
    const int WORDS = (N + 31) / 32;
    (void)n_in; (void)out_size;

    const int* row = ei;
    const int* col = ei + E;

    float* out1 = (float*)d_out;
    float* out2 = out1 + (size_t)N * 256;
    float* out3 = out2 + (size_t)E * 256;
    float* out4 = out3 + (size_t)N * 256;

    float *pP, *pQ, *pNbr, *pF2, *pS1, *pT1;
    cudaGetSymbolAddress((void**)&pP,  g_P);
    cudaGetSymbolAddress((void**)&pQ,  g_Q);
    cudaGetSymbolAddress((void**)&pNbr, g_nbr);
    cudaGetSymbolAddress((void**)&pF2, g_f2);
    cudaGetSymbolAddress((void**)&pS1, g_S1);
    cudaGetSymbolAddress((void**)&pT1, g_T1);

    cudaFuncSetAttribute(feat2_kernel, cudaFuncAttributeMaxDynamicSharedMemorySize,
                         F2_SMEM_TOTAL);
    cudaFuncSetAttribute(gemm_wmma, cudaFuncAttributeMaxDynamicSharedMemorySize, W8_TOTAL);

    int mt = (N + 127) / 128;

    const int BO_WN  = 0;
    const int BO_WET = 65536;
    const int BO_WEB = 131072;
    const int BO_WS1 = 196608;
    const int BO_WS2 = 327680;
    const int BO_WH1 = 393216;
    const int BO_WH2 = 589824;

    // (1) prep
    {
        PrepJob p0 = {Wn, 256, BO_WN};
        PrepJob p1 = {We, 256, BO_WET};
        PrepJob p2 = {We + (size_t)256 * 256, 256, BO_WEB};
        PrepJob p3 = {Ws1, 512, BO_WS1};
        PrepJob p4 = {Ws2, 256, BO_WS2};
        PrepJob p5 = {Wh1, 768, BO_WH1};
        PrepJob p6 = {Wh2, 256, BO_WH2};
        prep_kernel<<<512, 256>>>(p0, p1, p2, p3, p4, p5, p6, N, WORDS);
    }

    // (2) fused tokenizer GEMMs
    {
        GJob ja = {x, nullptr, nullptr, bn, out1, BO_WN, 1, 0};
        GJob jb = {x, nullptr, nullptr, be, pP,  BO_WET, 1, 0};
        GJob jc = {x, nullptr, nullptr, nullptr, pQ, BO_WEB, 1, 0};
        gemm_wmma<<<dim3(2, mt, 3), 256, W8_TOTAL>>>(ja, jb, jc, N);
    }

    // (3) edge_prep
    int eb = (E + 255) / 256;
    edge_prep_kernel<<<eb, 256>>>(row, col, E, WORDS);

    // (4) edge_tok  <- PROFILED SLOT (needs P,Q from launch 2)
    {
        long long etot = (long long)E * 64;
        int etb = (int)((etot + 255) / 256);
        edge_tok_kernel<<<etb, 256>>>(row, col, out2, E);
    }

    // (5) node_tokens -> bf16
    {
        int total4 = N * 64;
        nt2bf_kernel<<<(total4 + 255) / 256, 256>>>(out1, total4);
    }

    // (6) scan, (7) scatter, (8) hop1
    scan_kernel<<<1, 256>>>(N);
    scatter_kernel<<<eb, 256>>>(row, col, E);
    hop1_kernel<<<N, 256>>>(out1, N, WORDS);

    // (9) feat2 v4
    int f2grid = (N + F2_MI - 1) / F2_MI;
    feat2_kernel<<<dim3(f2grid, 2), 256, F2_SMEM_TOTAL>>>(N, WORDS);

    // (10) MLP layer 1
    {
        GJob ja = {out1, pNbr, nullptr, bs1, pS1, BO_WS1, 2, 1};
        GJob jb = {out1, pNbr, pF2,     bh1, pT1, BO_WH1, 3, 1};
        gemm_wmma<<<dim3(2, mt, 2), 256, W8_TOTAL>>>(ja, jb, ja, N);
    }
    // (11) MLP layer 2
    {
        GJob ja = {pS1, nullptr, nullptr, bs2, out3, BO_WS2, 1, 0};
        GJob jb = {pT1, nullptr, nullptr, bh2, out4, BO_WH2, 1, 0};
        gemm_wmma<<<dim3(2, mt, 2), 256, W8_TOTAL>>>(ja, jb, ja, N);
    }
}